// round 1
// baseline (speedup 1.0000x reference)
#include <cuda_runtime.h>

// out[b] = T[fwd_steps[b]-1] @ x[b]
// B=128, D=1024, K=100, fp32. Classic double-buffered SGEMM,
// tile 128x128, BK=16, 8x8 microtile per thread, 256 threads/CTA.

#define DDIM 1024
#define BM 128
#define BN 128
#define BK 16
#define NT 256

__global__ __launch_bounds__(NT, 2) void bgemm_f32_kernel(
    const float* __restrict__ Xin,     // [B, D, D]
    const int*   __restrict__ steps32, // fwd_steps viewed as int32 words
    const float* __restrict__ Tmat,    // [K, D, D]
    float*       __restrict__ Out)     // [B, D, D]
{
    const int b = blockIdx.z;

    // dtype sniff: int64 layout has high word 0 (values in [1,100]);
    // int32 layout has element 1 in [1,100] (never 0) at word index 1.
    const bool is64 = (steps32[1] == 0);
    const int kidx = (is64 ? steps32[2 * b] : steps32[b]) - 1;

    const float* __restrict__ A = Tmat + (size_t)kidx * DDIM * DDIM; // [D,D]
    const float* __restrict__ B = Xin  + (size_t)b    * DDIM * DDIM; // [D,D]
    float*       __restrict__ C = Out  + (size_t)b    * DDIM * DDIM; // [D,D]

    const int tm0 = blockIdx.y * BM;
    const int tn0 = blockIdx.x * BN;

    __shared__ float As[2][BK][BM];  // A tile stored transposed: [k][m]
    __shared__ float Bs[2][BK][BN];  // B tile: [k][n]

    const int tid = threadIdx.x;

    // A-tile load mapping: 128 rows x 16 cols, float4 per thread, 2 passes
    const int ar = tid >> 2;            // 0..63 (+64 on pass 1)
    const int ac = (tid & 3) << 2;      // 0,4,8,12
    // B-tile load mapping: 16 rows x 128 cols, float4 per thread, 2 passes
    const int br = tid >> 5;            // 0..7 (+8 on pass 1)
    const int bc = (tid & 31) << 2;     // 0..124

    // compute mapping: 16x16 thread grid, each does 8x8 (split 2x 4-vectors)
    const int tx = tid & 15;
    const int ty = tid >> 4;

    float acc[8][8];
    #pragma unroll
    for (int i = 0; i < 8; ++i)
        #pragma unroll
        for (int j = 0; j < 8; ++j)
            acc[i][j] = 0.0f;

    float4 pa[2], pb[2];

    // ---- prologue: load stage 0 ----
    {
        const int k0 = 0;
        #pragma unroll
        for (int p = 0; p < 2; ++p)
            pa[p] = *reinterpret_cast<const float4*>(
                &A[(size_t)(tm0 + ar + 64 * p) * DDIM + k0 + ac]);
        #pragma unroll
        for (int p = 0; p < 2; ++p)
            pb[p] = *reinterpret_cast<const float4*>(
                &B[(size_t)(k0 + br + 8 * p) * DDIM + tn0 + bc]);
        #pragma unroll
        for (int p = 0; p < 2; ++p) {
            As[0][ac + 0][ar + 64 * p] = pa[p].x;
            As[0][ac + 1][ar + 64 * p] = pa[p].y;
            As[0][ac + 2][ar + 64 * p] = pa[p].z;
            As[0][ac + 3][ar + 64 * p] = pa[p].w;
            *reinterpret_cast<float4*>(&Bs[0][br + 8 * p][bc]) = pb[p];
        }
    }
    __syncthreads();

    int buf = 0;
    const int KT = DDIM / BK;  // 64

    for (int kt = 0; kt < KT; ++kt) {
        // issue next-stage global loads early
        if (kt + 1 < KT) {
            const int k0 = (kt + 1) * BK;
            #pragma unroll
            for (int p = 0; p < 2; ++p)
                pa[p] = *reinterpret_cast<const float4*>(
                    &A[(size_t)(tm0 + ar + 64 * p) * DDIM + k0 + ac]);
            #pragma unroll
            for (int p = 0; p < 2; ++p)
                pb[p] = *reinterpret_cast<const float4*>(
                    &B[(size_t)(k0 + br + 8 * p) * DDIM + tn0 + bc]);
        }

        // compute on current buffer
        #pragma unroll
        for (int kk = 0; kk < BK; ++kk) {
            float4 a0 = *reinterpret_cast<const float4*>(&As[buf][kk][ty * 4]);
            float4 a1 = *reinterpret_cast<const float4*>(&As[buf][kk][64 + ty * 4]);
            float4 b0 = *reinterpret_cast<const float4*>(&Bs[buf][kk][tx * 4]);
            float4 b1 = *reinterpret_cast<const float4*>(&Bs[buf][kk][64 + tx * 4]);
            float af[8] = {a0.x, a0.y, a0.z, a0.w, a1.x, a1.y, a1.z, a1.w};
            float bf[8] = {b0.x, b0.y, b0.z, b0.w, b1.x, b1.y, b1.z, b1.w};
            #pragma unroll
            for (int i = 0; i < 8; ++i)
                #pragma unroll
                for (int j = 0; j < 8; ++j)
                    acc[i][j] = fmaf(af[i], bf[j], acc[i][j]);
        }

        // commit next stage to the other smem buffer
        if (kt + 1 < KT) {
            const int nb = buf ^ 1;
            #pragma unroll
            for (int p = 0; p < 2; ++p) {
                As[nb][ac + 0][ar + 64 * p] = pa[p].x;
                As[nb][ac + 1][ar + 64 * p] = pa[p].y;
                As[nb][ac + 2][ar + 64 * p] = pa[p].z;
                As[nb][ac + 3][ar + 64 * p] = pa[p].w;
                *reinterpret_cast<float4*>(&Bs[nb][br + 8 * p][bc]) = pb[p];
            }
            __syncthreads();
            buf = nb;
        }
    }

    // ---- epilogue: vectorized stores ----
    #pragma unroll
    for (int ih = 0; ih < 2; ++ih) {
        #pragma unroll
        for (int i = 0; i < 4; ++i) {
            const int row = tm0 + ih * 64 + ty * 4 + i;
            float* cp = &C[(size_t)row * DDIM + tn0];
            float4 v0 = make_float4(acc[ih * 4 + i][0], acc[ih * 4 + i][1],
                                    acc[ih * 4 + i][2], acc[ih * 4 + i][3]);
            float4 v1 = make_float4(acc[ih * 4 + i][4], acc[ih * 4 + i][5],
                                    acc[ih * 4 + i][6], acc[ih * 4 + i][7]);
            *reinterpret_cast<float4*>(&cp[tx * 4])      = v0;
            *reinterpret_cast<float4*>(&cp[64 + tx * 4]) = v1;
        }
    }
}

extern "C" void kernel_launch(void* const* d_in, const int* in_sizes, int n_in,
                              void* d_out, int out_size) {
    const float* x     = (const float*)d_in[0];
    const int*   steps = (const int*)d_in[1];   // int32 or int64 words, sniffed in-kernel
    const float* T     = (const float*)d_in[2];
    float* out = (float*)d_out;

    dim3 grid(DDIM / BN, DDIM / BM, 128);  // (8, 8, 128)
    bgemm_f32_kernel<<<grid, NT>>>(x, steps, T, out);
}

// round 4
// speedup vs baseline: 2.0017x; 2.0017x over previous
#include <cuda_runtime.h>
#include <cuda_bf16.h>
#include <cstdint>

// out[b] = T[fwd_steps[b]-1] @ x[b];  B=128, D=1024, fp32.
// Tensor-core bgemm via family-portable mma.sync bf16 with Markidis 3-product
// split (hi*hi + hi*lo + lo*hi), fp32 accumulate. 128x128 tile, BK=32 fp32,
// double-buffered smem, 8 warps (2m x 4n), warp tile 64x32.

#define DDIM 1024
#define BKF 32
#define NCH (DDIM / BKF)          // 32 chunks

#define A_STR 80                  // bytes per A row (32 bf16 + 8 pad)
#define B_STR 272                 // bytes per B row (128 bf16 + 8 pad)
#define A_VER 10240               // A lo-version offset (128*80)
#define B_OFF 20480               // B base within stage
#define B_VER 8704                // B lo-version offset (32*272)
#define STAGE 37888               // A(2*10240) + B(2*8704)
#define SMEM_TOTAL (2 * STAGE)    // 75776

__device__ __forceinline__ uint32_t smem_u32(const void* p) {
    uint32_t a;
    asm("{ .reg .u64 t; cvta.to.shared.u64 t, %1; cvt.u32.u64 %0, t; }" : "=r"(a) : "l"(p));
    return a;
}

__device__ __forceinline__ void ldsm4(uint32_t (&r)[4], uint32_t addr) {
    asm volatile("ldmatrix.sync.aligned.m8n8.x4.shared.b16 {%0,%1,%2,%3}, [%4];"
                 : "=r"(r[0]), "=r"(r[1]), "=r"(r[2]), "=r"(r[3]) : "r"(addr));
}
__device__ __forceinline__ void ldsm4t(uint32_t (&r)[4], uint32_t addr) {
    asm volatile("ldmatrix.sync.aligned.m8n8.x4.trans.shared.b16 {%0,%1,%2,%3}, [%4];"
                 : "=r"(r[0]), "=r"(r[1]), "=r"(r[2]), "=r"(r[3]) : "r"(addr));
}
__device__ __forceinline__ void mma_bf16(float (&d)[4], const uint32_t (&a)[4],
                                         uint32_t b0, uint32_t b1) {
    asm volatile(
        "mma.sync.aligned.m16n8k16.row.col.f32.bf16.bf16.f32 "
        "{%0,%1,%2,%3}, {%4,%5,%6,%7}, {%8,%9}, {%0,%1,%2,%3};"
        : "+f"(d[0]), "+f"(d[1]), "+f"(d[2]), "+f"(d[3])
        : "r"(a[0]), "r"(a[1]), "r"(a[2]), "r"(a[3]), "r"(b0), "r"(b1));
}

// split two fp32 into packed bf16 hi-pair and lo-pair (residual)
__device__ __forceinline__ void split2(float x, float y, uint32_t& hp, uint32_t& lp) {
    __nv_bfloat16 hx = __float2bfloat16_rn(x);
    __nv_bfloat16 hy = __float2bfloat16_rn(y);
    float rx = x - __bfloat162float(hx);
    float ry = y - __bfloat162float(hy);
    __nv_bfloat16 lx = __float2bfloat16_rn(rx);
    __nv_bfloat16 ly = __float2bfloat16_rn(ry);
    hp = (uint32_t)__bfloat16_as_ushort(hx) | ((uint32_t)__bfloat16_as_ushort(hy) << 16);
    lp = (uint32_t)__bfloat16_as_ushort(lx) | ((uint32_t)__bfloat16_as_ushort(ly) << 16);
}
__device__ __forceinline__ void split4(float4 v, uint2& hi, uint2& lo) {
    split2(v.x, v.y, hi.x, lo.x);
    split2(v.z, v.w, hi.y, lo.y);
}

// one k16 step: 12 ldmatrix + 48 mma (3 products over 4m x 4n tiles)
__device__ __forceinline__ void do_k16(uint32_t sb, uint32_t stg, int k16,
                                       int warp_m, int warp_n, int lane,
                                       float (&acc)[4][4][4]) {
    const uint32_t lrow = lane & 15;
    const uint32_t lsel = lane >> 4;
    const uint32_t a_off = sb + stg + (warp_m * 64 + lrow) * A_STR +
                           (k16 * 16 + lsel * 8) * 2;
    const uint32_t b_off = sb + stg + B_OFF + (k16 * 16 + lrow) * B_STR +
                           (warp_n * 32 + lsel * 8) * 2;

    uint32_t bh[2][4], bl[2][4], a[4][4];
    #pragma unroll
    for (int g = 0; g < 2; ++g) ldsm4t(bh[g], b_off + g * 32);
    #pragma unroll
    for (int g = 0; g < 2; ++g) ldsm4t(bl[g], b_off + B_VER + g * 32);
    #pragma unroll
    for (int mt = 0; mt < 4; ++mt) ldsm4(a[mt], a_off + mt * (16 * A_STR));

    #pragma unroll
    for (int mt = 0; mt < 4; ++mt)
        #pragma unroll
        for (int nt = 0; nt < 4; ++nt)
            mma_bf16(acc[mt][nt], a[mt], bh[nt >> 1][(nt & 1) * 2], bh[nt >> 1][(nt & 1) * 2 + 1]);
    #pragma unroll
    for (int mt = 0; mt < 4; ++mt)
        #pragma unroll
        for (int nt = 0; nt < 4; ++nt)
            mma_bf16(acc[mt][nt], a[mt], bl[nt >> 1][(nt & 1) * 2], bl[nt >> 1][(nt & 1) * 2 + 1]);
    #pragma unroll
    for (int mt = 0; mt < 4; ++mt) ldsm4(a[mt], a_off + A_VER + mt * (16 * A_STR));
    #pragma unroll
    for (int mt = 0; mt < 4; ++mt)
        #pragma unroll
        for (int nt = 0; nt < 4; ++nt)
            mma_bf16(acc[mt][nt], a[mt], bh[nt >> 1][(nt & 1) * 2], bh[nt >> 1][(nt & 1) * 2 + 1]);
}

__device__ __forceinline__ void ldg_a(const float* __restrict__ Ag, int tm0, int kc,
                                      int tid, float4 (&av)[4]) {
    const int row = tid >> 3;
    const int col = (tid & 7) * 4;
    #pragma unroll
    for (int p = 0; p < 4; ++p)
        av[p] = *reinterpret_cast<const float4*>(
            Ag + (size_t)(tm0 + row + 32 * p) * DDIM + kc + col);
}
__device__ __forceinline__ void sts_a(char* smem, uint32_t stg, int tid,
                                      const float4 (&av)[4]) {
    const int row = tid >> 3;
    const int col = (tid & 7) * 4;
    #pragma unroll
    for (int p = 0; p < 4; ++p) {
        uint2 hi, lo;
        split4(av[p], hi, lo);
        const uint32_t off = stg + (row + 32 * p) * A_STR + col * 2;
        *reinterpret_cast<uint2*>(smem + off)         = hi;
        *reinterpret_cast<uint2*>(smem + off + A_VER) = lo;
    }
}
__device__ __forceinline__ void ldg_b(const float* __restrict__ Bg, int tn0, int kc,
                                      int tid, float4 (&bv)[4]) {
    const int k = tid >> 5;
    const int n = (tid & 31) * 4;
    #pragma unroll
    for (int p = 0; p < 4; ++p)
        bv[p] = *reinterpret_cast<const float4*>(
            Bg + (size_t)(kc + k + 8 * p) * DDIM + tn0 + n);
}
__device__ __forceinline__ void sts_b(char* smem, uint32_t stg, int tid,
                                      const float4 (&bv)[4]) {
    const int k = tid >> 5;
    const int n = (tid & 31) * 4;
    #pragma unroll
    for (int p = 0; p < 4; ++p) {
        uint2 hi, lo;
        split4(bv[p], hi, lo);
        const uint32_t off = stg + B_OFF + (k + 8 * p) * B_STR + n * 2;
        *reinterpret_cast<uint2*>(smem + off)         = hi;
        *reinterpret_cast<uint2*>(smem + off + B_VER) = lo;
    }
}

__global__ __launch_bounds__(256, 2) void bgemm_mma_kernel(
    const float* __restrict__ Xin,     // [B, D, D]
    const int*   __restrict__ steps32, // fwd_steps (int32 or int64 words)
    const float* __restrict__ Tmat,    // [K, D, D]
    float*       __restrict__ Out)     // [B, D, D]
{
    extern __shared__ char smem[];
    const uint32_t sb = smem_u32(smem);
    const int tid  = threadIdx.x;
    const int lane = tid & 31;
    const int wid  = tid >> 5;
    const int warp_m = wid & 1;   // 2 warps over M
    const int warp_n = wid >> 1;  // 4 warps over N

    const int b = blockIdx.z;
    const bool is64 = (steps32[1] == 0);
    const int kidx = (is64 ? steps32[2 * b] : steps32[b]) - 1;

    const float* __restrict__ Ag = Tmat + (size_t)kidx * DDIM * DDIM;
    const float* __restrict__ Bg = Xin  + (size_t)b    * DDIM * DDIM;
    float*       __restrict__ Cg = Out  + (size_t)b    * DDIM * DDIM;

    const int tm0 = blockIdx.y * 128;
    const int tn0 = blockIdx.x * 128;

    float acc[4][4][4];
    #pragma unroll
    for (int i = 0; i < 4; ++i)
        #pragma unroll
        for (int j = 0; j < 4; ++j)
            #pragma unroll
            for (int q = 0; q < 4; ++q)
                acc[i][j][q] = 0.0f;

    // prologue: fill stage 0
    {
        float4 av[4], bv[4];
        ldg_a(Ag, tm0, 0, tid, av);
        ldg_b(Bg, tn0, 0, tid, bv);
        sts_a(smem, 0, tid, av);
        sts_b(smem, 0, tid, bv);
    }
    __syncthreads();

    for (int c = 0; c < NCH; ++c) {
        const uint32_t stg_cur = (uint32_t)(c & 1) * STAGE;
        const uint32_t stg_nxt = stg_cur ^ STAGE;
        const bool has_next = (c + 1 < NCH);
        const int kc_next = (c + 1) * BKF;

        float4 av[4];
        if (has_next) ldg_a(Ag, tm0, kc_next, tid, av);

        do_k16(sb, stg_cur, 0, warp_m, warp_n, lane, acc);

        if (has_next) sts_a(smem, stg_nxt, tid, av);

        float4 bv[4];
        if (has_next) ldg_b(Bg, tn0, kc_next, tid, bv);

        do_k16(sb, stg_cur, 1, warp_m, warp_n, lane, acc);

        if (has_next) sts_b(smem, stg_nxt, tid, bv);
        __syncthreads();
    }

    // epilogue: d0,d1 -> (row g, col 2t), d2,d3 -> (row g+8)
    const int g = lane >> 2;
    const int t = lane & 3;
    #pragma unroll
    for (int mt = 0; mt < 4; ++mt) {
        #pragma unroll
        for (int nt = 0; nt < 4; ++nt) {
            const int row = tm0 + warp_m * 64 + mt * 16 + g;
            const int col = tn0 + warp_n * 32 + nt * 8 + t * 2;
            *reinterpret_cast<float2*>(Cg + (size_t)row * DDIM + col) =
                make_float2(acc[mt][nt][0], acc[mt][nt][1]);
            *reinterpret_cast<float2*>(Cg + (size_t)(row + 8) * DDIM + col) =
                make_float2(acc[mt][nt][2], acc[mt][nt][3]);
        }
    }
}

extern "C" void kernel_launch(void* const* d_in, const int* in_sizes, int n_in,
                              void* d_out, int out_size) {
    const float* x     = (const float*)d_in[0];
    const int*   steps = (const int*)d_in[1];
    const float* T     = (const float*)d_in[2];
    float* out = (float*)d_out;

    cudaFuncSetAttribute(bgemm_mma_kernel,
                         cudaFuncAttributeMaxDynamicSharedMemorySize, SMEM_TOTAL);
    dim3 grid(DDIM / 128, DDIM / 128, 128);  // (8, 8, 128)
    bgemm_mma_kernel<<<grid, 256, SMEM_TOTAL>>>(x, steps, T, out);
}